// round 2
// baseline (speedup 1.0000x reference)
#include <cuda_runtime.h>
#include <math.h>

#define ROWS   4096      // B*T
#define DMOD   1024
#define DI     1024
#define DS     16
#define TLEN   2048
#define BSZ    2
#define N2     2048      // 2*DI
#define KCONV  4

// ---------------- scratch (device globals; no runtime allocation) ----------
__device__ float g_xn[ROWS * DMOD];        // layernorm output
__device__ float g_xz[(size_t)ROWS * N2];  // xn @ W_in  (cols 0..1023 = x_ssm pre-conv, 1024.. = z)
__device__ float g_xs[ROWS * DI];          // conv + silu output
__device__ float g_dt[ROWS * DI];          // softplus(x @ dt_w + dt_b)
__device__ float g_wbc[DI * 2 * DS];       // combined [DI][32] = [B_w | C_w]
__device__ float g_bc[ROWS * 2 * DS];      // per-row [32] = [Bm | Cm]
__device__ float g_yg[ROWS * DI];          // gated scan output (input to W_out GEMM)

__device__ __forceinline__ float siluf(float v)     { return v / (1.f + expf(-v)); }
__device__ __forceinline__ float softplusf(float v) { return v > 20.f ? v : log1pf(expf(v)); }

// ---------------- LayerNorm: one block per row ------------------------------
__global__ void ln_kernel(const float* __restrict__ x, const float* __restrict__ g,
                          const float* __restrict__ b, float* __restrict__ out) {
    __shared__ float ssum[8], ssq[8];
    int row = blockIdx.x;
    int tid = threadIdx.x;
    const float4* xr = (const float4*)(x + (size_t)row * DMOD);
    float4 v = xr[tid];
    float s = v.x + v.y + v.z + v.w;
    float q = v.x * v.x + v.y * v.y + v.z * v.z + v.w * v.w;
    #pragma unroll
    for (int o = 16; o; o >>= 1) {
        s += __shfl_xor_sync(0xffffffffu, s, o);
        q += __shfl_xor_sync(0xffffffffu, q, o);
    }
    if ((tid & 31) == 0) { ssum[tid >> 5] = s; ssq[tid >> 5] = q; }
    __syncthreads();
    s = 0.f; q = 0.f;
    #pragma unroll
    for (int i = 0; i < 8; i++) { s += ssum[i]; q += ssq[i]; }
    float mean = s * (1.f / DMOD);
    float var  = q * (1.f / DMOD) - mean * mean;
    float rstd = rsqrtf(var + 1e-5f);
    float4 gg = ((const float4*)g)[tid];
    float4 bb = ((const float4*)b)[tid];
    float4 o4;
    o4.x = (v.x - mean) * rstd * gg.x + bb.x;
    o4.y = (v.y - mean) * rstd * gg.y + bb.y;
    o4.z = (v.z - mean) * rstd * gg.z + bb.z;
    o4.w = (v.w - mean) * rstd * gg.w + bb.w;
    ((float4*)(out + (size_t)row * DMOD))[tid] = o4;
}

// ---------------- SGEMM 128x128x8, double buffered, 8x8/thread --------------
// MODE 0: C = A*B ; MODE 1: C = softplus(A*B + bias[n]) ; MODE 2: C = A*B + add[m,n]
template <int MODE>
__global__ void __launch_bounds__(256)
sgemm_kernel(const float* __restrict__ A, const float* __restrict__ B,
             float* __restrict__ C, int M, int N, int K,
             const float* __restrict__ bias, const float* __restrict__ add) {
    __shared__ float As[2][8][128];
    __shared__ float Bs[2][8][128];
    int tid  = threadIdx.x;
    int row0 = blockIdx.y * 128;
    int col0 = blockIdx.x * 128;

    int aRow = tid >> 1,  aCol = (tid & 1) << 2;   // A tile 128x8: 1 float4/thread
    int bRow = tid >> 5,  bCol = (tid & 31) << 2;  // B tile 8x128: 1 float4/thread
    const float* Aptr = A + (size_t)(row0 + aRow) * K + aCol;
    const float* Bptr = B + (size_t)bRow * N + col0 + bCol;

    float4 a4 = *(const float4*)Aptr;
    float4 b4 = *(const float4*)Bptr;
    As[0][aCol + 0][aRow] = a4.x; As[0][aCol + 1][aRow] = a4.y;
    As[0][aCol + 2][aRow] = a4.z; As[0][aCol + 3][aRow] = a4.w;
    *(float4*)&Bs[0][bRow][bCol] = b4;
    __syncthreads();

    float acc[8][8];
    #pragma unroll
    for (int i = 0; i < 8; i++)
        #pragma unroll
        for (int j = 0; j < 8; j++) acc[i][j] = 0.f;

    int ty = tid >> 4, tx = tid & 15;
    int KT = K >> 3;
    for (int kt = 0; kt < KT; kt++) {
        int cur = kt & 1;
        if (kt + 1 < KT) {
            a4 = *(const float4*)(Aptr + (kt + 1) * 8);
            b4 = *(const float4*)(Bptr + (size_t)(kt + 1) * 8 * N);
        }
        #pragma unroll
        for (int k = 0; k < 8; k++) {
            float4 x0 = *(float4*)&As[cur][k][ty * 8];
            float4 x1 = *(float4*)&As[cur][k][ty * 8 + 4];
            float4 y0 = *(float4*)&Bs[cur][k][tx * 8];
            float4 y1 = *(float4*)&Bs[cur][k][tx * 8 + 4];
            float av[8] = {x0.x, x0.y, x0.z, x0.w, x1.x, x1.y, x1.z, x1.w};
            float bv[8] = {y0.x, y0.y, y0.z, y0.w, y1.x, y1.y, y1.z, y1.w};
            #pragma unroll
            for (int i = 0; i < 8; i++)
                #pragma unroll
                for (int j = 0; j < 8; j++) acc[i][j] += av[i] * bv[j];
        }
        if (kt + 1 < KT) {
            int nxt = cur ^ 1;
            As[nxt][aCol + 0][aRow] = a4.x; As[nxt][aCol + 1][aRow] = a4.y;
            As[nxt][aCol + 2][aRow] = a4.z; As[nxt][aCol + 3][aRow] = a4.w;
            *(float4*)&Bs[nxt][bRow][bCol] = b4;
        }
        __syncthreads();
    }

    #pragma unroll
    for (int i = 0; i < 8; i++) {
        int r = row0 + ty * 8 + i;
        #pragma unroll
        for (int jj = 0; jj < 2; jj++) {
            int cc = col0 + tx * 8 + jj * 4;
            float4 v = make_float4(acc[i][jj * 4 + 0], acc[i][jj * 4 + 1],
                                   acc[i][jj * 4 + 2], acc[i][jj * 4 + 3]);
            if (MODE == 1) {
                float4 bb = *(const float4*)(bias + cc);
                v.x = softplusf(v.x + bb.x); v.y = softplusf(v.y + bb.y);
                v.z = softplusf(v.z + bb.z); v.w = softplusf(v.w + bb.w);
            }
            if (MODE == 2) {
                float4 aa = *(const float4*)(add + (size_t)r * N + cc);
                v.x += aa.x; v.y += aa.y; v.z += aa.z; v.w += aa.w;
            }
            *(float4*)(C + (size_t)r * N + cc) = v;
        }
    }
}

// ---------------- causal depthwise conv (K=4) + bias + silu -----------------
__global__ void conv_silu_kernel(const float* __restrict__ w,
                                 const float* __restrict__ cb) {
    int idx = blockIdx.x * blockDim.x + threadIdx.x;   // over ROWS*DI
    if (idx >= ROWS * DI) return;
    int d   = idx & (DI - 1);
    int row = idx >> 10;
    int t   = row & (TLEN - 1);
    float acc = cb[d];
    #pragma unroll
    for (int k = 0; k < KCONV; k++) {
        int tt = t + k - (KCONV - 1);
        if (tt >= 0)
            acc += w[d * KCONV + k] * g_xz[(size_t)(row + k - (KCONV - 1)) * N2 + d];
    }
    g_xs[idx] = siluf(acc);
}

// ---------------- pack [B_w | C_w] into [DI][32] -----------------------------
__global__ void prep_wbc_kernel(const float* __restrict__ Bw, const float* __restrict__ Cw) {
    int idx = blockIdx.x * blockDim.x + threadIdx.x;   // over DI*DS
    if (idx >= DI * DS) return;
    int d = idx >> 4, s = idx & 15;
    g_wbc[d * 32 + s]      = Bw[idx];
    g_wbc[d * 32 + 16 + s] = Cw[idx];
}

// ---------------- Bm/Cm skinny GEMM: one warp per row, lane = output col ----
__global__ void bc_kernel() {
    int warp = blockIdx.x * (blockDim.x >> 5) + (threadIdx.x >> 5);  // row id
    int lane = threadIdx.x & 31;
    const float* xr = g_xs + (size_t)warp * DI;
    float acc = 0.f;
    #pragma unroll 8
    for (int d = 0; d < DI; d++)
        acc += xr[d] * g_wbc[d * 32 + lane];
    g_bc[warp * 32 + lane] = acc;
}

// ---------------- selective scan, parallel over (b,d,s) ---------------------
// Fuses: y = (scan + x*D) * silu(z)
__global__ void scan_kernel(const float* __restrict__ log_A,
                            const float* __restrict__ Dp) {
    int tid = blockIdx.x * blockDim.x + threadIdx.x;   // over BSZ*DI*DS = 32768
    int s = tid & 15;
    int c = tid >> 4;            // channel = b*DI + d
    int d = c & (DI - 1);
    int b = c >> 10;
    float A  = -__expf(log_A[d]);
    float Dv = Dp[d];
    float h = 0.f;
    int base = b * TLEN;
    #pragma unroll 2
    for (int t = 0; t < TLEN; t++) {
        int row   = base + t;
        float dtv = g_dt[(size_t)row * DI + d];
        float xv  = g_xs[(size_t)row * DI + d];
        float bv  = g_bc[row * 32 + s];
        float cv  = g_bc[row * 32 + 16 + s];
        float a   = __expf(fminf(dtv * A, 0.f));
        h = h * a + dtv * xv * bv;
        float y = h * cv;
        y += __shfl_xor_sync(0xffffffffu, y, 8);
        y += __shfl_xor_sync(0xffffffffu, y, 4);
        y += __shfl_xor_sync(0xffffffffu, y, 2);
        y += __shfl_xor_sync(0xffffffffu, y, 1);
        if (s == 0) {
            float zv = g_xz[(size_t)row * N2 + DI + d];
            g_yg[(size_t)row * DI + d] = (y + xv * Dv) * siluf(zv);
        }
    }
}

// ---------------- launch ----------------------------------------------------
extern "C" void kernel_launch(void* const* d_in, const int* in_sizes, int n_in,
                              void* d_out, int out_size) {
    const float* x      = (const float*)d_in[0];
    const float* ln_g   = (const float*)d_in[1];
    const float* ln_b   = (const float*)d_in[2];
    const float* W_in   = (const float*)d_in[3];
    const float* conv_w = (const float*)d_in[4];
    const float* conv_b = (const float*)d_in[5];
    const float* dt_w   = (const float*)d_in[6];
    const float* dt_b   = (const float*)d_in[7];
    const float* B_w    = (const float*)d_in[8];
    const float* C_w    = (const float*)d_in[9];
    const float* log_A  = (const float*)d_in[10];
    const float* D_par  = (const float*)d_in[11];
    const float* W_out  = (const float*)d_in[12];
    float* out = (float*)d_out;

    float *xn, *xz, *xs, *dt, *yg;
    cudaGetSymbolAddress((void**)&xn, g_xn);
    cudaGetSymbolAddress((void**)&xz, g_xz);
    cudaGetSymbolAddress((void**)&xs, g_xs);
    cudaGetSymbolAddress((void**)&dt, g_dt);
    cudaGetSymbolAddress((void**)&yg, g_yg);

    // 1. LayerNorm
    ln_kernel<<<ROWS, 256>>>(x, ln_g, ln_b, xn);
    // 2. xz = xn @ W_in  [4096 x 2048]
    sgemm_kernel<0><<<dim3(N2 / 128, ROWS / 128), 256>>>(xn, W_in, xz, ROWS, N2, DMOD, nullptr, nullptr);
    // 3. causal depthwise conv + silu -> x_ssm
    conv_silu_kernel<<<(ROWS * DI) / 256, 256>>>(conv_w, conv_b);
    // 4. pack B_w/C_w
    prep_wbc_kernel<<<(DI * DS) / 256, 256>>>(B_w, C_w);
    // 5. dt = softplus(x_ssm @ dt_w + dt_b)
    sgemm_kernel<1><<<dim3(DI / 128, ROWS / 128), 256>>>(xs, dt_w, dt, ROWS, DI, DI, dt_b, nullptr);
    // 6. Bm, Cm
    bc_kernel<<<ROWS / 8, 256>>>();
    // 7. selective scan + D-skip + silu(z) gate
    scan_kernel<<<(BSZ * DI * DS) / 128, 128>>>(log_A, D_par);
    // 8. out = residual + yg @ W_out
    sgemm_kernel<2><<<dim3(DMOD / 128, ROWS / 128), 256>>>(yg, W_out, out, ROWS, DMOD, DI, nullptr, x);
}

// round 4
// speedup vs baseline: 1.1694x; 1.1694x over previous
#include <cuda_runtime.h>
#include <cuda_bf16.h>
#include <cstdint>
#include <math.h>

#define ROWS   4096      // B*T
#define DMOD   1024
#define DI     1024
#define DS     16
#define TLEN   2048
#define BSZ    2
#define N2     2048      // 2*DI
#define KCONV  4

// ---------------- scratch (device globals; no runtime allocation) ----------
__device__ float g_xz[(size_t)ROWS * N2];  // xn @ W_in (fp32: x-part for conv, z-part for gate)
__device__ float g_xs[ROWS * DI];          // conv + silu output fp32 (scan, bc)
__device__ float g_dt[ROWS * DI];          // softplus(x @ dt_w + dt_b)
__device__ float g_wbc[DI * 2 * DS];       // [DI][32] = [B_w | C_w]
__device__ float g_bc[ROWS * 2 * DS];      // per-row [32] = [Bm | Cm]

// bf16 hi/lo split activations (GEMM A operands)
__device__ __nv_bfloat16 g_xn_h[ROWS * DMOD], g_xn_l[ROWS * DMOD];
__device__ __nv_bfloat16 g_xs_h[ROWS * DI],   g_xs_l[ROWS * DI];
__device__ __nv_bfloat16 g_yg_h[ROWS * DI],   g_yg_l[ROWS * DI];

// transposed + bf16 hi/lo split weights  (WT[n][k] = W[k][n])
__device__ __nv_bfloat16 g_WinT_h[(size_t)N2 * DMOD], g_WinT_l[(size_t)N2 * DMOD];
__device__ __nv_bfloat16 g_dtwT_h[DI * DI],           g_dtwT_l[DI * DI];
__device__ __nv_bfloat16 g_WoutT_h[DI * DMOD],        g_WoutT_l[DI * DMOD];

__device__ __forceinline__ float siluf(float v)     { return v / (1.f + expf(-v)); }
__device__ __forceinline__ float softplusf(float v) { return v > 20.f ? v : log1pf(expf(v)); }

__device__ __forceinline__ uint32_t smem_to_u32(const void* p) {
    uint32_t a;
    asm("{ .reg .u64 t; cvta.to.shared.u64 t, %1; cvt.u32.u64 %0, t; }" : "=r"(a) : "l"(p));
    return a;
}
__device__ __forceinline__ void cp_async16(uint32_t dst, const void* src) {
    asm volatile("cp.async.cg.shared.global [%0], [%1], 16;" :: "r"(dst), "l"(src));
}
#define CP_COMMIT() asm volatile("cp.async.commit_group;" ::: "memory")
#define CP_WAIT1()  asm volatile("cp.async.wait_group 1;" ::: "memory")

__device__ __forceinline__ void ldm_x4(uint32_t* r, uint32_t addr) {
    asm volatile("ldmatrix.sync.aligned.m8n8.x4.shared.b16 {%0,%1,%2,%3}, [%4];"
        : "=r"(r[0]), "=r"(r[1]), "=r"(r[2]), "=r"(r[3]) : "r"(addr));
}
__device__ __forceinline__ void mma_bf16(float* d, const uint32_t* a, const uint32_t* b) {
    asm volatile("mma.sync.aligned.m16n8k16.row.col.f32.bf16.bf16.f32 "
        "{%0,%1,%2,%3}, {%4,%5,%6,%7}, {%8,%9}, {%0,%1,%2,%3};"
        : "+f"(d[0]), "+f"(d[1]), "+f"(d[2]), "+f"(d[3])
        : "r"(a[0]), "r"(a[1]), "r"(a[2]), "r"(a[3]), "r"(b[0]), "r"(b[1]));
}
__device__ __forceinline__ void split_bf(float v, __nv_bfloat16& h, __nv_bfloat16& l) {
    h = __float2bfloat16(v);
    l = __float2bfloat16(v - __bfloat162float(h));
}

// ---------------- LayerNorm: one block per row, outputs bf16 hi/lo ----------
__global__ void ln_kernel(const float* __restrict__ x, const float* __restrict__ g,
                          const float* __restrict__ b,
                          __nv_bfloat16* __restrict__ oh, __nv_bfloat16* __restrict__ ol) {
    __shared__ float ssum[8], ssq[8];
    int row = blockIdx.x;
    int tid = threadIdx.x;
    const float4* xr = (const float4*)(x + (size_t)row * DMOD);
    float4 v = xr[tid];
    float s = v.x + v.y + v.z + v.w;
    float q = v.x * v.x + v.y * v.y + v.z * v.z + v.w * v.w;
    #pragma unroll
    for (int o = 16; o; o >>= 1) {
        s += __shfl_xor_sync(0xffffffffu, s, o);
        q += __shfl_xor_sync(0xffffffffu, q, o);
    }
    if ((tid & 31) == 0) { ssum[tid >> 5] = s; ssq[tid >> 5] = q; }
    __syncthreads();
    s = 0.f; q = 0.f;
    #pragma unroll
    for (int i = 0; i < 8; i++) { s += ssum[i]; q += ssq[i]; }
    float mean = s * (1.f / DMOD);
    float var  = q * (1.f / DMOD) - mean * mean;
    float rstd = rsqrtf(var + 1e-5f);
    float4 gg = ((const float4*)g)[tid];
    float4 bb = ((const float4*)b)[tid];
    float o0 = (v.x - mean) * rstd * gg.x + bb.x;
    float o1 = (v.y - mean) * rstd * gg.y + bb.y;
    float o2 = (v.z - mean) * rstd * gg.z + bb.z;
    float o3 = (v.w - mean) * rstd * gg.w + bb.w;
    __nv_bfloat16 h0, h1, h2, h3, l0, l1, l2, l3;
    split_bf(o0, h0, l0); split_bf(o1, h1, l1);
    split_bf(o2, h2, l2); split_bf(o3, h3, l3);
    size_t o = (size_t)row * DMOD + tid * 4;
    ((__nv_bfloat162*)(oh + o))[0] = __nv_bfloat162(h0, h1);
    ((__nv_bfloat162*)(oh + o))[1] = __nv_bfloat162(h2, h3);
    ((__nv_bfloat162*)(ol + o))[0] = __nv_bfloat162(l0, l1);
    ((__nv_bfloat162*)(ol + o))[1] = __nv_bfloat162(l2, l3);
}

// ---------------- transpose + bf16 hi/lo split ------------------------------
__global__ void tsplit_kernel(const float* __restrict__ W,
                              __nv_bfloat16* __restrict__ hi,
                              __nv_bfloat16* __restrict__ lo, int K, int N) {
    __shared__ float t[32][33];
    int k0 = blockIdx.y * 32, n0 = blockIdx.x * 32;
    int tx = threadIdx.x, ty = threadIdx.y;
    #pragma unroll
    for (int i = ty; i < 32; i += 8)
        t[i][tx] = W[(size_t)(k0 + i) * N + n0 + tx];
    __syncthreads();
    #pragma unroll
    for (int i = ty; i < 32; i += 8) {
        float v = t[tx][i];
        __nv_bfloat16 h, l;
        split_bf(v, h, l);
        size_t o = (size_t)(n0 + i) * K + k0 + tx;
        hi[o] = h; lo[o] = l;
    }
}

// ---------------- tensor-core GEMM via mma.sync bf16, 3-pass hi/lo ----------
// C[M,N] = A[M,K] * B[N,K]^T   (A,B pre-split bf16 hi/lo, K-major)
// MODE 0: C = P ; MODE 1: C = softplus(P + bias[n]) ; MODE 2: C = P + add[m,n]
#define BK       32
#define LDT      40                 // smem row stride in bf16 (80 B, ldmatrix conflict-free)
#define TILE_B   (128 * LDT * 2)    // 10240 B per tile
#define STAGE_B  (4 * TILE_B)       // Ah, Al, Bh, Bl
#define MM_SMEM  (2 * STAGE_B)      // 81920 B

template <int MODE>
__global__ void __launch_bounds__(256, 1)
mm_kernel(const __nv_bfloat16* __restrict__ Ah, const __nv_bfloat16* __restrict__ Al,
          const __nv_bfloat16* __restrict__ Bh, const __nv_bfloat16* __restrict__ Bl,
          float* __restrict__ C, int M, int N, int K,
          const float* __restrict__ bias, const float* __restrict__ add) {
    extern __shared__ char smem[];
    uint32_t sb = smem_to_u32(smem);

    int tid = threadIdx.x, wid = tid >> 5, lane = tid & 31;
    int row0 = blockIdx.y * 128, col0 = blockIdx.x * 128;
    int wm = wid >> 2, wn = wid & 3;            // warp tile 64x32 at (wm*64, wn*32)

    // loader mapping: each thread covers half a 64B row-chunk in each tile
    int lr = tid >> 1, lh = tid & 1;
    uint32_t soff = (uint32_t)lr * (LDT * 2) + lh * 32;
    const __nv_bfloat16* gA_h = Ah + (size_t)(row0 + lr) * K + lh * 16;
    const __nv_bfloat16* gA_l = Al + (size_t)(row0 + lr) * K + lh * 16;
    const __nv_bfloat16* gB_h = Bh + (size_t)(col0 + lr) * K + lh * 16;
    const __nv_bfloat16* gB_l = Bl + (size_t)(col0 + lr) * K + lh * 16;

    // fragment addresses
    int a_row = wm * 64 + (lane & 15);
    int a_kh  = (lane >> 4) << 3;                       // 0 / 8
    int b_row = wn * 32 + (lane & 7) + ((lane >> 4) << 3);
    int b_kh  = ((lane >> 3) & 1) << 3;

    float acc[4][4][4];
    #pragma unroll
    for (int i = 0; i < 4; i++)
        #pragma unroll
        for (int j = 0; j < 4; j++)
            #pragma unroll
            for (int r = 0; r < 4; r++) acc[i][j][r] = 0.f;

    const int NC = K / BK;

    // prologue: stage 0 <- chunk 0
    {
        cp_async16(sb + 0 * TILE_B + soff,      gA_h);
        cp_async16(sb + 0 * TILE_B + soff + 16, gA_h + 8);
        cp_async16(sb + 1 * TILE_B + soff,      gA_l);
        cp_async16(sb + 1 * TILE_B + soff + 16, gA_l + 8);
        cp_async16(sb + 2 * TILE_B + soff,      gB_h);
        cp_async16(sb + 2 * TILE_B + soff + 16, gB_h + 8);
        cp_async16(sb + 3 * TILE_B + soff,      gB_l);
        cp_async16(sb + 3 * TILE_B + soff + 16, gB_l + 8);
        CP_COMMIT();
    }

    for (int c = 0; c < NC; c++) {
        if (c + 1 < NC) {
            uint32_t st = sb + ((c + 1) & 1) * STAGE_B;
            int kc = (c + 1) * BK;
            cp_async16(st + 0 * TILE_B + soff,      gA_h + kc);
            cp_async16(st + 0 * TILE_B + soff + 16, gA_h + kc + 8);
            cp_async16(st + 1 * TILE_B + soff,      gA_l + kc);
            cp_async16(st + 1 * TILE_B + soff + 16, gA_l + kc + 8);
            cp_async16(st + 2 * TILE_B + soff,      gB_h + kc);
            cp_async16(st + 2 * TILE_B + soff + 16, gB_h + kc + 8);
            cp_async16(st + 3 * TILE_B + soff,      gB_l + kc);
            cp_async16(st + 3 * TILE_B + soff + 16, gB_l + kc + 8);
        }
        CP_COMMIT();
        CP_WAIT1();
        __syncthreads();

        uint32_t st = sb + (c & 1) * STAGE_B;
        #pragma unroll
        for (int kk = 0; kk < BK; kk += 16) {
            uint32_t af_h[4][4], af_l[4][4], bf_h[2][4], bf_l[2][4];
            #pragma unroll
            for (int mi = 0; mi < 4; mi++) {
                uint32_t ao = st + (uint32_t)(a_row + mi * 16) * (LDT * 2) + (kk + a_kh) * 2;
                ldm_x4(af_h[mi], ao + 0 * TILE_B);
                ldm_x4(af_l[mi], ao + 1 * TILE_B);
            }
            #pragma unroll
            for (int n2 = 0; n2 < 2; n2++) {
                uint32_t bo = st + (uint32_t)(b_row + n2 * 16) * (LDT * 2) + (kk + b_kh) * 2;
                ldm_x4(bf_h[n2], bo + 2 * TILE_B);
                ldm_x4(bf_l[n2], bo + 3 * TILE_B);
            }
            #pragma unroll
            for (int mi = 0; mi < 4; mi++)
                #pragma unroll
                for (int ni = 0; ni < 4; ni++) {
                    const uint32_t* bh = &bf_h[ni >> 1][(ni & 1) * 2];
                    const uint32_t* bl = &bf_l[ni >> 1][(ni & 1) * 2];
                    mma_bf16(acc[mi][ni], af_h[mi], bh);
                    mma_bf16(acc[mi][ni], af_h[mi], bl);
                    mma_bf16(acc[mi][ni], af_l[mi], bh);
                }
        }
        __syncthreads();
    }

    // ---- epilogue: registers -> gmem
    #pragma unroll
    for (int mi = 0; mi < 4; mi++) {
        int r0 = row0 + wm * 64 + mi * 16 + (lane >> 2);
        #pragma unroll
        for (int ni = 0; ni < 4; ni++) {
            int cc = col0 + wn * 32 + ni * 8 + (lane & 3) * 2;
            #pragma unroll
            for (int hh = 0; hh < 2; hh++) {
                int rr = r0 + hh * 8;
                float v0 = acc[mi][ni][hh * 2 + 0];
                float v1 = acc[mi][ni][hh * 2 + 1];
                if (MODE == 1) {
                    float2 bb = *(const float2*)(bias + cc);
                    v0 = softplusf(v0 + bb.x);
                    v1 = softplusf(v1 + bb.y);
                }
                if (MODE == 2) {
                    float2 aa = *(const float2*)(add + (size_t)rr * N + cc);
                    v0 += aa.x; v1 += aa.y;
                }
                *(float2*)(C + (size_t)rr * N + cc) = make_float2(v0, v1);
            }
        }
    }
}

// ---------------- causal depthwise conv (K=4) + bias + silu -----------------
// writes fp32 (for scan/bc) and bf16 hi/lo (for dt GEMM)
__global__ void conv_silu_kernel(const float* __restrict__ w,
                                 const float* __restrict__ cb) {
    int idx = blockIdx.x * blockDim.x + threadIdx.x;   // over ROWS*DI
    if (idx >= ROWS * DI) return;
    int d   = idx & (DI - 1);
    int row = idx >> 10;
    int t   = row & (TLEN - 1);
    float acc = cb[d];
    #pragma unroll
    for (int k = 0; k < KCONV; k++) {
        int tt = t + k - (KCONV - 1);
        if (tt >= 0)
            acc += w[d * KCONV + k] * g_xz[(size_t)(row + k - (KCONV - 1)) * N2 + d];
    }
    float v = siluf(acc);
    g_xs[idx] = v;
    __nv_bfloat16 h, l;
    split_bf(v, h, l);
    g_xs_h[idx] = h; g_xs_l[idx] = l;
}

// ---------------- pack [B_w | C_w] into [DI][32] -----------------------------
__global__ void prep_wbc_kernel(const float* __restrict__ Bw, const float* __restrict__ Cw) {
    int idx = blockIdx.x * blockDim.x + threadIdx.x;
    if (idx >= DI * DS) return;
    int d = idx >> 4, s = idx & 15;
    g_wbc[d * 32 + s]      = Bw[idx];
    g_wbc[d * 32 + 16 + s] = Cw[idx];
}

// ---------------- Bm/Cm skinny GEMM: one warp per row -----------------------
__global__ void bc_kernel() {
    int warp = blockIdx.x * (blockDim.x >> 5) + (threadIdx.x >> 5);
    int lane = threadIdx.x & 31;
    const float* xr = g_xs + (size_t)warp * DI;
    float acc = 0.f;
    #pragma unroll 8
    for (int d = 0; d < DI; d++)
        acc += xr[d] * g_wbc[d * 32 + lane];
    g_bc[warp * 32 + lane] = acc;
}

// ---------------- selective scan, parallel over (b,d,s) ---------------------
// Fuses: yg = (scan + x*D) * silu(z), written as bf16 hi/lo for the out GEMM
__global__ void scan_kernel(const float* __restrict__ log_A,
                            const float* __restrict__ Dp) {
    int tid = blockIdx.x * blockDim.x + threadIdx.x;   // over BSZ*DI*DS = 32768
    int s = tid & 15;
    int c = tid >> 4;
    int d = c & (DI - 1);
    int b = c >> 10;
    float A  = -__expf(log_A[d]);
    float Dv = Dp[d];
    float h = 0.f;
    int base = b * TLEN;
    #pragma unroll 2
    for (int t = 0; t < TLEN; t++) {
        int row   = base + t;
        float dtv = g_dt[(size_t)row * DI + d];
        float xv  = g_xs[(size_t)row * DI + d];
        float bv  = g_bc[row * 32 + s];
        float cv  = g_bc[row * 32 + 16 + s];
        float a   = __expf(fminf(dtv * A, 0.f));
        h = h * a + dtv * xv * bv;
        float y = h * cv;
        y += __shfl_xor_sync(0xffffffffu, y, 8);
        y += __shfl_xor_sync(0xffffffffu, y, 4);
        y += __shfl_xor_sync(0xffffffffu, y, 2);
        y += __shfl_xor_sync(0xffffffffu, y, 1);
        if (s == 0) {
            float zv = g_xz[(size_t)row * N2 + DI + d];
            float yv = (y + xv * Dv) * siluf(zv);
            __nv_bfloat16 hh, ll;
            split_bf(yv, hh, ll);
            size_t o = (size_t)row * DI + d;
            g_yg_h[o] = hh; g_yg_l[o] = ll;
        }
    }
}

// ---------------- launch ----------------------------------------------------
extern "C" void kernel_launch(void* const* d_in, const int* in_sizes, int n_in,
                              void* d_out, int out_size) {
    const float* x      = (const float*)d_in[0];
    const float* ln_g   = (const float*)d_in[1];
    const float* ln_b   = (const float*)d_in[2];
    const float* W_in   = (const float*)d_in[3];
    const float* conv_w = (const float*)d_in[4];
    const float* conv_b = (const float*)d_in[5];
    const float* dt_w   = (const float*)d_in[6];
    const float* dt_b   = (const float*)d_in[7];
    const float* B_w    = (const float*)d_in[8];
    const float* C_w    = (const float*)d_in[9];
    const float* log_A  = (const float*)d_in[10];
    const float* D_par  = (const float*)d_in[11];
    const float* W_out  = (const float*)d_in[12];
    float* out = (float*)d_out;

    float *xz, *dt;
    __nv_bfloat16 *xnh, *xnl, *xsh, *xsl, *ygh, *ygl;
    __nv_bfloat16 *winh, *winl, *dtwh, *dtwl, *wouh, *woul;
    cudaGetSymbolAddress((void**)&xz,  g_xz);
    cudaGetSymbolAddress((void**)&dt,  g_dt);
    cudaGetSymbolAddress((void**)&xnh, g_xn_h);  cudaGetSymbolAddress((void**)&xnl, g_xn_l);
    cudaGetSymbolAddress((void**)&xsh, g_xs_h);  cudaGetSymbolAddress((void**)&xsl, g_xs_l);
    cudaGetSymbolAddress((void**)&ygh, g_yg_h);  cudaGetSymbolAddress((void**)&ygl, g_yg_l);
    cudaGetSymbolAddress((void**)&winh, g_WinT_h); cudaGetSymbolAddress((void**)&winl, g_WinT_l);
    cudaGetSymbolAddress((void**)&dtwh, g_dtwT_h); cudaGetSymbolAddress((void**)&dtwl, g_dtwT_l);
    cudaGetSymbolAddress((void**)&wouh, g_WoutT_h); cudaGetSymbolAddress((void**)&woul, g_WoutT_l);

    cudaFuncSetAttribute(mm_kernel<0>, cudaFuncAttributeMaxDynamicSharedMemorySize, MM_SMEM);
    cudaFuncSetAttribute(mm_kernel<1>, cudaFuncAttributeMaxDynamicSharedMemorySize, MM_SMEM);
    cudaFuncSetAttribute(mm_kernel<2>, cudaFuncAttributeMaxDynamicSharedMemorySize, MM_SMEM);

    dim3 tb(32, 8);
    // weight preprocessing (transpose + bf16 hi/lo split)
    tsplit_kernel<<<dim3(N2 / 32, DMOD / 32), tb>>>(W_in,  winh, winl, DMOD, N2);
    tsplit_kernel<<<dim3(DI / 32, DI / 32),   tb>>>(dt_w,  dtwh, dtwl, DI, DI);
    tsplit_kernel<<<dim3(DMOD / 32, DI / 32), tb>>>(W_out, wouh, woul, DI, DMOD);

    // 1. LayerNorm (-> bf16 hi/lo)
    ln_kernel<<<ROWS, 256>>>(x, ln_g, ln_b, xnh, xnl);
    // 2. xz = xn @ W_in
    mm_kernel<0><<<dim3(N2 / 128, ROWS / 128), 256, MM_SMEM>>>(
        xnh, xnl, winh, winl, xz, ROWS, N2, DMOD, nullptr, nullptr);
    // 3. conv + silu (-> fp32 + bf16 hi/lo)
    conv_silu_kernel<<<(ROWS * DI) / 256, 256>>>(conv_w, conv_b);
    // 4. pack B_w/C_w
    prep_wbc_kernel<<<(DI * DS) / 256, 256>>>(B_w, C_w);
    // 5. dt = softplus(x_ssm @ dt_w + dt_b)
    mm_kernel<1><<<dim3(DI / 128, ROWS / 128), 256, MM_SMEM>>>(
        xsh, xsl, dtwh, dtwl, dt, ROWS, DI, DI, dt_b, nullptr);
    // 6. Bm, Cm
    bc_kernel<<<ROWS / 8, 256>>>();
    // 7. selective scan + D-skip + silu(z) gate (-> bf16 hi/lo)
    scan_kernel<<<(BSZ * DI * DS) / 128, 128>>>(log_A, D_par);
    // 8. out = residual + yg @ W_out
    mm_kernel<2><<<dim3(DMOD / 128, ROWS / 128), 256, MM_SMEM>>>(
        ygh, ygl, wouh, woul, out, ROWS, DMOD, DI, nullptr, x);
}

// round 5
// speedup vs baseline: 1.2406x; 1.0609x over previous
#include <cuda_runtime.h>
#include <cuda_fp16.h>
#include <cstdint>
#include <math.h>

#define ROWS   4096      // B*T
#define DMOD   1024
#define DI     1024
#define DS     16
#define TLEN   2048
#define BSZ    2
#define N2     2048      // 2*DI
#define KCONV  4

// ---------------- scratch (device globals; no runtime allocation) ----------
__device__ float g_xz[(size_t)ROWS * N2];  // xn @ W_in (fp32: x-part for conv, z-part for gate)
__device__ float g_xs[ROWS * DI];          // conv + silu output fp32 (scan, bc)
__device__ float g_dt[ROWS * DI];          // softplus(x @ dt_w + dt_b)
__device__ float g_wbc[DI * 2 * DS];       // [DI][32] = [B_w | C_w]
__device__ float g_bc[ROWS * 2 * DS];      // per-row [32] = [Bm | Cm]

// fp16 hi/lo split activations (GEMM A operands)
__device__ __half g_xn_h[ROWS * DMOD], g_xn_l[ROWS * DMOD];
__device__ __half g_xs_h[ROWS * DI],   g_xs_l[ROWS * DI];
__device__ __half g_yg_h[ROWS * DI],   g_yg_l[ROWS * DI];

// transposed fp16 weights (single precision pass)  WT[n][k] = W[k][n]
__device__ __half g_WinT[(size_t)N2 * DMOD];
__device__ __half g_dtwT[DI * DI];
__device__ __half g_WoutT[DI * DMOD];

__device__ __forceinline__ float siluf(float v)     { return v / (1.f + expf(-v)); }
__device__ __forceinline__ float softplusf(float v) { return v > 20.f ? v : log1pf(expf(v)); }

__device__ __forceinline__ uint32_t smem_to_u32(const void* p) {
    uint32_t a;
    asm("{ .reg .u64 t; cvta.to.shared.u64 t, %1; cvt.u32.u64 %0, t; }" : "=r"(a) : "l"(p));
    return a;
}
__device__ __forceinline__ void cp_async16(uint32_t dst, const void* src) {
    asm volatile("cp.async.cg.shared.global [%0], [%1], 16;" :: "r"(dst), "l"(src));
}
#define CP_COMMIT() asm volatile("cp.async.commit_group;" ::: "memory")
#define CP_WAIT1()  asm volatile("cp.async.wait_group 1;" ::: "memory")

__device__ __forceinline__ void ldm_x4(uint32_t* r, uint32_t addr) {
    asm volatile("ldmatrix.sync.aligned.m8n8.x4.shared.b16 {%0,%1,%2,%3}, [%4];"
        : "=r"(r[0]), "=r"(r[1]), "=r"(r[2]), "=r"(r[3]) : "r"(addr));
}
__device__ __forceinline__ void mma_f16(float* d, const uint32_t* a, const uint32_t* b) {
    asm volatile("mma.sync.aligned.m16n8k16.row.col.f32.f16.f16.f32 "
        "{%0,%1,%2,%3}, {%4,%5,%6,%7}, {%8,%9}, {%0,%1,%2,%3};"
        : "+f"(d[0]), "+f"(d[1]), "+f"(d[2]), "+f"(d[3])
        : "r"(a[0]), "r"(a[1]), "r"(a[2]), "r"(a[3]), "r"(b[0]), "r"(b[1]));
}
__device__ __forceinline__ void split_h(float v, __half& h, __half& l) {
    h = __float2half(v);
    l = __float2half(v - __half2float(h));
}

// ---------------- LayerNorm: one block per row, outputs fp16 hi/lo ----------
__global__ void ln_kernel(const float* __restrict__ x, const float* __restrict__ g,
                          const float* __restrict__ b,
                          __half* __restrict__ oh, __half* __restrict__ ol) {
    __shared__ float ssum[8], ssq[8];
    int row = blockIdx.x;
    int tid = threadIdx.x;
    const float4* xr = (const float4*)(x + (size_t)row * DMOD);
    float4 v = xr[tid];
    float s = v.x + v.y + v.z + v.w;
    float q = v.x * v.x + v.y * v.y + v.z * v.z + v.w * v.w;
    #pragma unroll
    for (int o = 16; o; o >>= 1) {
        s += __shfl_xor_sync(0xffffffffu, s, o);
        q += __shfl_xor_sync(0xffffffffu, q, o);
    }
    if ((tid & 31) == 0) { ssum[tid >> 5] = s; ssq[tid >> 5] = q; }
    __syncthreads();
    s = 0.f; q = 0.f;
    #pragma unroll
    for (int i = 0; i < 8; i++) { s += ssum[i]; q += ssq[i]; }
    float mean = s * (1.f / DMOD);
    float var  = q * (1.f / DMOD) - mean * mean;
    float rstd = rsqrtf(var + 1e-5f);
    float4 gg = ((const float4*)g)[tid];
    float4 bb = ((const float4*)b)[tid];
    float o0 = (v.x - mean) * rstd * gg.x + bb.x;
    float o1 = (v.y - mean) * rstd * gg.y + bb.y;
    float o2 = (v.z - mean) * rstd * gg.z + bb.z;
    float o3 = (v.w - mean) * rstd * gg.w + bb.w;
    __half h0, h1, h2, h3, l0, l1, l2, l3;
    split_h(o0, h0, l0); split_h(o1, h1, l1);
    split_h(o2, h2, l2); split_h(o3, h3, l3);
    size_t o = (size_t)row * DMOD + tid * 4;
    ((__half2*)(oh + o))[0] = __halves2half2(h0, h1);
    ((__half2*)(oh + o))[1] = __halves2half2(h2, h3);
    ((__half2*)(ol + o))[0] = __halves2half2(l0, l1);
    ((__half2*)(ol + o))[1] = __halves2half2(l2, l3);
}

// ---------------- transpose + fp16 convert ----------------------------------
__global__ void tsplit_kernel(const float* __restrict__ W,
                              __half* __restrict__ out, int K, int N) {
    __shared__ float t[32][33];
    int k0 = blockIdx.y * 32, n0 = blockIdx.x * 32;
    int tx = threadIdx.x, ty = threadIdx.y;
    #pragma unroll
    for (int i = ty; i < 32; i += 8)
        t[i][tx] = W[(size_t)(k0 + i) * N + n0 + tx];
    __syncthreads();
    #pragma unroll
    for (int i = ty; i < 32; i += 8)
        out[(size_t)(n0 + i) * K + k0 + tx] = __float2half(t[tx][i]);
}

// ---------------- tensor-core GEMM via mma.sync fp16, 2-pass hi/lo A --------
// C[M,N] = A[M,K] * B[N,K]^T   (A fp16 hi/lo, B single fp16, K-major)
// MODE 0: C = P ; MODE 1: C = softplus(P + bias[n]) ; MODE 2: C = P + add[m,n]
#define BK       32
#define LDT      40                 // smem row stride in fp16 (80 B, ldmatrix conflict-free)
#define TILE_B   (128 * LDT * 2)    // 10240 B per tile
#define STAGE_B  (3 * TILE_B)       // Ah, Al, B
#define MM_SMEM  (2 * STAGE_B)      // 61440 B

template <int MODE>
__global__ void __launch_bounds__(256, 1)
mm_kernel(const __half* __restrict__ Ah, const __half* __restrict__ Al,
          const __half* __restrict__ Bw,
          float* __restrict__ C, int M, int N, int K,
          const float* __restrict__ bias, const float* __restrict__ add) {
    extern __shared__ char smem[];
    uint32_t sb = smem_to_u32(smem);

    int tid = threadIdx.x, wid = tid >> 5, lane = tid & 31;
    int row0 = blockIdx.y * 128, col0 = blockIdx.x * 128;
    int wm = wid >> 2, wn = wid & 3;            // warp tile 64x32 at (wm*64, wn*32)

    // loader mapping: each thread covers half a 64B row-chunk in each tile
    int lr = tid >> 1, lh = tid & 1;
    uint32_t soff = (uint32_t)lr * (LDT * 2) + lh * 32;
    const __half* gA_h = Ah + (size_t)(row0 + lr) * K + lh * 16;
    const __half* gA_l = Al + (size_t)(row0 + lr) * K + lh * 16;
    const __half* gB   = Bw + (size_t)(col0 + lr) * K + lh * 16;

    // fragment addresses
    int a_row = wm * 64 + (lane & 15);
    int a_kh  = (lane >> 4) << 3;                       // 0 / 8
    int b_row = wn * 32 + (lane & 7) + ((lane >> 4) << 3);
    int b_kh  = ((lane >> 3) & 1) << 3;

    float acc[4][4][4];
    #pragma unroll
    for (int i = 0; i < 4; i++)
        #pragma unroll
        for (int j = 0; j < 4; j++)
            #pragma unroll
            for (int r = 0; r < 4; r++) acc[i][j][r] = 0.f;

    const int NC = K / BK;

    // prologue: stage 0 <- chunk 0
    {
        cp_async16(sb + 0 * TILE_B + soff,      gA_h);
        cp_async16(sb + 0 * TILE_B + soff + 16, gA_h + 8);
        cp_async16(sb + 1 * TILE_B + soff,      gA_l);
        cp_async16(sb + 1 * TILE_B + soff + 16, gA_l + 8);
        cp_async16(sb + 2 * TILE_B + soff,      gB);
        cp_async16(sb + 2 * TILE_B + soff + 16, gB + 8);
        CP_COMMIT();
    }

    for (int c = 0; c < NC; c++) {
        if (c + 1 < NC) {
            uint32_t st = sb + ((c + 1) & 1) * STAGE_B;
            int kc = (c + 1) * BK;
            cp_async16(st + 0 * TILE_B + soff,      gA_h + kc);
            cp_async16(st + 0 * TILE_B + soff + 16, gA_h + kc + 8);
            cp_async16(st + 1 * TILE_B + soff,      gA_l + kc);
            cp_async16(st + 1 * TILE_B + soff + 16, gA_l + kc + 8);
            cp_async16(st + 2 * TILE_B + soff,      gB + kc);
            cp_async16(st + 2 * TILE_B + soff + 16, gB + kc + 8);
        }
        CP_COMMIT();
        CP_WAIT1();
        __syncthreads();

        uint32_t st = sb + (c & 1) * STAGE_B;
        #pragma unroll
        for (int kk = 0; kk < BK; kk += 16) {
            uint32_t af_h[4][4], af_l[4][4], bf[2][4];
            #pragma unroll
            for (int mi = 0; mi < 4; mi++) {
                uint32_t ao = st + (uint32_t)(a_row + mi * 16) * (LDT * 2) + (kk + a_kh) * 2;
                ldm_x4(af_h[mi], ao + 0 * TILE_B);
                ldm_x4(af_l[mi], ao + 1 * TILE_B);
            }
            #pragma unroll
            for (int n2 = 0; n2 < 2; n2++) {
                uint32_t bo = st + (uint32_t)(b_row + n2 * 16) * (LDT * 2) + (kk + b_kh) * 2;
                ldm_x4(bf[n2], bo + 2 * TILE_B);
            }
            // pass-major ordering: 16 independent MMAs per pass
            #pragma unroll
            for (int mi = 0; mi < 4; mi++)
                #pragma unroll
                for (int ni = 0; ni < 4; ni++)
                    mma_f16(acc[mi][ni], af_h[mi], &bf[ni >> 1][(ni & 1) * 2]);
            #pragma unroll
            for (int mi = 0; mi < 4; mi++)
                #pragma unroll
                for (int ni = 0; ni < 4; ni++)
                    mma_f16(acc[mi][ni], af_l[mi], &bf[ni >> 1][(ni & 1) * 2]);
        }
        __syncthreads();
    }

    // ---- epilogue: registers -> gmem
    #pragma unroll
    for (int mi = 0; mi < 4; mi++) {
        int r0 = row0 + wm * 64 + mi * 16 + (lane >> 2);
        #pragma unroll
        for (int ni = 0; ni < 4; ni++) {
            int cc = col0 + wn * 32 + ni * 8 + (lane & 3) * 2;
            #pragma unroll
            for (int hh = 0; hh < 2; hh++) {
                int rr = r0 + hh * 8;
                float v0 = acc[mi][ni][hh * 2 + 0];
                float v1 = acc[mi][ni][hh * 2 + 1];
                if (MODE == 1) {
                    float2 bb = *(const float2*)(bias + cc);
                    v0 = softplusf(v0 + bb.x);
                    v1 = softplusf(v1 + bb.y);
                }
                if (MODE == 2) {
                    float2 aa = *(const float2*)(add + (size_t)rr * N + cc);
                    v0 += aa.x; v1 += aa.y;
                }
                *(float2*)(C + (size_t)rr * N + cc) = make_float2(v0, v1);
            }
        }
    }
}

// ---------------- causal depthwise conv (K=4) + bias + silu -----------------
// writes fp32 (for scan/bc) and fp16 hi/lo (for dt GEMM)
__global__ void conv_silu_kernel(const float* __restrict__ w,
                                 const float* __restrict__ cb) {
    int idx = blockIdx.x * blockDim.x + threadIdx.x;   // over ROWS*DI
    if (idx >= ROWS * DI) return;
    int d   = idx & (DI - 1);
    int row = idx >> 10;
    int t   = row & (TLEN - 1);
    float acc = cb[d];
    #pragma unroll
    for (int k = 0; k < KCONV; k++) {
        int tt = t + k - (KCONV - 1);
        if (tt >= 0)
            acc += w[d * KCONV + k] * g_xz[(size_t)(row + k - (KCONV - 1)) * N2 + d];
    }
    float v = siluf(acc);
    g_xs[idx] = v;
    __half h, l;
    split_h(v, h, l);
    g_xs_h[idx] = h; g_xs_l[idx] = l;
}

// ---------------- pack [B_w | C_w] into [DI][32] -----------------------------
__global__ void prep_wbc_kernel(const float* __restrict__ Bw, const float* __restrict__ Cw) {
    int idx = blockIdx.x * blockDim.x + threadIdx.x;
    if (idx >= DI * DS) return;
    int d = idx >> 4, s = idx & 15;
    g_wbc[d * 32 + s]      = Bw[idx];
    g_wbc[d * 32 + 16 + s] = Cw[idx];
}

// ---------------- Bm/Cm skinny GEMM: one warp per row -----------------------
__global__ void bc_kernel() {
    int warp = blockIdx.x * (blockDim.x >> 5) + (threadIdx.x >> 5);
    int lane = threadIdx.x & 31;
    const float* xr = g_xs + (size_t)warp * DI;
    float acc = 0.f;
    #pragma unroll 8
    for (int d = 0; d < DI; d++)
        acc += xr[d] * g_wbc[d * 32 + lane];
    g_bc[warp * 32 + lane] = acc;
}

// ---------------- selective scan, parallel over (b,d,s) ---------------------
// Fuses: yg = (scan + x*D) * silu(z), written as fp16 hi/lo for the out GEMM
__global__ void scan_kernel(const float* __restrict__ log_A,
                            const float* __restrict__ Dp) {
    int tid = blockIdx.x * blockDim.x + threadIdx.x;   // over BSZ*DI*DS = 32768
    int s = tid & 15;
    int c = tid >> 4;
    int d = c & (DI - 1);
    int b = c >> 10;
    float A  = -__expf(log_A[d]);
    float Dv = Dp[d];
    float h = 0.f;
    int base = b * TLEN;
    #pragma unroll 2
    for (int t = 0; t < TLEN; t++) {
        int row   = base + t;
        float dtv = g_dt[(size_t)row * DI + d];
        float xv  = g_xs[(size_t)row * DI + d];
        float bv  = g_bc[row * 32 + s];
        float cv  = g_bc[row * 32 + 16 + s];
        float a   = __expf(fminf(dtv * A, 0.f));
        h = h * a + dtv * xv * bv;
        float y = h * cv;
        y += __shfl_xor_sync(0xffffffffu, y, 8);
        y += __shfl_xor_sync(0xffffffffu, y, 4);
        y += __shfl_xor_sync(0xffffffffu, y, 2);
        y += __shfl_xor_sync(0xffffffffu, y, 1);
        if (s == 0) {
            float zv = g_xz[(size_t)row * N2 + DI + d];
            float yv = (y + xv * Dv) * siluf(zv);
            __half hh, ll;
            split_h(yv, hh, ll);
            size_t o = (size_t)row * DI + d;
            g_yg_h[o] = hh; g_yg_l[o] = ll;
        }
    }
}

// ---------------- launch ----------------------------------------------------
extern "C" void kernel_launch(void* const* d_in, const int* in_sizes, int n_in,
                              void* d_out, int out_size) {
    const float* x      = (const float*)d_in[0];
    const float* ln_g   = (const float*)d_in[1];
    const float* ln_b   = (const float*)d_in[2];
    const float* W_in   = (const float*)d_in[3];
    const float* conv_w = (const float*)d_in[4];
    const float* conv_b = (const float*)d_in[5];
    const float* dt_w   = (const float*)d_in[6];
    const float* dt_b   = (const float*)d_in[7];
    const float* B_w    = (const float*)d_in[8];
    const float* C_w    = (const float*)d_in[9];
    const float* log_A  = (const float*)d_in[10];
    const float* D_par  = (const float*)d_in[11];
    const float* W_out  = (const float*)d_in[12];
    float* out = (float*)d_out;

    __half *xnh, *xnl, *xsh, *xsl, *ygh, *ygl, *winT, *dtwT, *wouT;
    cudaGetSymbolAddress((void**)&xnh, g_xn_h);  cudaGetSymbolAddress((void**)&xnl, g_xn_l);
    cudaGetSymbolAddress((void**)&xsh, g_xs_h);  cudaGetSymbolAddress((void**)&xsl, g_xs_l);
    cudaGetSymbolAddress((void**)&ygh, g_yg_h);  cudaGetSymbolAddress((void**)&ygl, g_yg_l);
    cudaGetSymbolAddress((void**)&winT, g_WinT);
    cudaGetSymbolAddress((void**)&dtwT, g_dtwT);
    cudaGetSymbolAddress((void**)&wouT, g_WoutT);
    float *xz, *dt;
    cudaGetSymbolAddress((void**)&xz, g_xz);
    cudaGetSymbolAddress((void**)&dt, g_dt);

    cudaFuncSetAttribute(mm_kernel<0>, cudaFuncAttributeMaxDynamicSharedMemorySize, MM_SMEM);
    cudaFuncSetAttribute(mm_kernel<1>, cudaFuncAttributeMaxDynamicSharedMemorySize, MM_SMEM);
    cudaFuncSetAttribute(mm_kernel<2>, cudaFuncAttributeMaxDynamicSharedMemorySize, MM_SMEM);

    dim3 tb(32, 8);
    // weight preprocessing (transpose + fp16 convert)
    tsplit_kernel<<<dim3(N2 / 32, DMOD / 32), tb>>>(W_in,  winT, DMOD, N2);
    tsplit_kernel<<<dim3(DI / 32, DI / 32),   tb>>>(dt_w,  dtwT, DI, DI);
    tsplit_kernel<<<dim3(DMOD / 32, DI / 32), tb>>>(W_out, wouT, DI, DMOD);

    // 1. LayerNorm (-> fp16 hi/lo)
    ln_kernel<<<ROWS, 256>>>(x, ln_g, ln_b, xnh, xnl);
    // 2. xz = xn @ W_in
    mm_kernel<0><<<dim3(N2 / 128, ROWS / 128), 256, MM_SMEM>>>(
        xnh, xnl, winT, xz, ROWS, N2, DMOD, nullptr, nullptr);
    // 3. conv + silu (-> fp32 + fp16 hi/lo)
    conv_silu_kernel<<<(ROWS * DI) / 256, 256>>>(conv_w, conv_b);
    // 4. pack B_w/C_w
    prep_wbc_kernel<<<(DI * DS) / 256, 256>>>(B_w, C_w);
    // 5. dt = softplus(x_ssm @ dt_w + dt_b)
    mm_kernel<1><<<dim3(DI / 128, ROWS / 128), 256, MM_SMEM>>>(
        xsh, xsl, dtwT, dt, ROWS, DI, DI, dt_b, nullptr);
    // 6. Bm, Cm
    bc_kernel<<<ROWS / 8, 256>>>();
    // 7. selective scan + D-skip + silu(z) gate (-> fp16 hi/lo)
    scan_kernel<<<(BSZ * DI * DS) / 128, 128>>>(log_A, D_par);
    // 8. out = residual + yg @ W_out
    mm_kernel<2><<<dim3(DMOD / 128, ROWS / 128), 256, MM_SMEM>>>(
        ygh, ygl, wouT, out, ROWS, DMOD, DI, nullptr, x);
}